// round 5
// baseline (speedup 1.0000x reference)
#include <cuda_runtime.h>
#include <cuda_bf16.h>

// Problem constants (max sizes; actual N/E taken from in_sizes)
#define MAXN 170000
#define DF   128     // D_IN and H*D
#define HEADS 4
#define DH   32
#define NEG_SLOPE 0.2f

// -------- scratch (device globals; no allocations allowed) --------
__device__ __align__(16) float g_h[MAXN * DF];      // node projections h = x @ W_embed
__device__ __align__(16) float g_acc[MAXN * DF];    // unnormalized aggregation
__device__ __align__(16) float g_ds[MAXN * HEADS];  // dot_src
__device__ __align__(16) float g_dd[MAXN * HEADS];  // dot_dst
__device__ __align__(16) float g_den[MAXN * HEADS]; // softmax denominators

// ---------------- zero accumulators -------------------------------
// float4 units: acc = N*32, denom = N (N*4 floats)
__global__ void zero_kernel(int n) {
    int idx = blockIdx.x * blockDim.x + threadIdx.x;
    int acc4 = n * 32;
    float4 z = make_float4(0.f, 0.f, 0.f, 0.f);
    if (idx < acc4) {
        ((float4*)g_acc)[idx] = z;
    } else if (idx < acc4 + n) {
        ((float4*)g_den)[idx - acc4] = z;
    }
}

// ---------------- fused dual GEMM ---------------------------------
// out tiles: by in {0,1} -> W_embed cols -> g_h ; by in {2,3} -> W_lin cols -> d_out (+bias)
// BM=64, BN=64, BK=16, 256 threads, 4x4 microtile per thread.
__global__ void gemm_kernel(const float* __restrict__ x,
                            const float* __restrict__ W_embed,
                            const float* __restrict__ W_lin,
                            const float* __restrict__ bias,
                            float* __restrict__ lin_out,
                            int N)
{
    __shared__ __align__(16) float As[16][64];
    __shared__ __align__(16) float Bs[16][64];

    int by = blockIdx.y;                       // 0..3
    const float* W = (by < 2) ? W_embed : W_lin;
    float* Out     = (by < 2) ? g_h : lin_out;
    int colOff = (by & 1) * 64;

    int tid = threadIdx.x;                     // 0..255
    int tx = tid & 15;
    int ty = tid >> 4;
    int rowBase = blockIdx.x * 64;

    // loader indices
    int lrow = tid >> 2;          // 0..63
    int lk   = (tid & 3) * 4;     // 0,4,8,12
    int brow = tid >> 4;          // 0..15
    int bcol = (tid & 15) * 4;    // 0..60

    float acc[4][4];
    #pragma unroll
    for (int i = 0; i < 4; i++)
        #pragma unroll
        for (int j = 0; j < 4; j++) acc[i][j] = 0.f;

    int gr = rowBase + lrow;

    for (int k0 = 0; k0 < DF; k0 += 16) {
        float4 av = make_float4(0.f, 0.f, 0.f, 0.f);
        if (gr < N) av = *(const float4*)&x[gr * DF + k0 + lk];
        As[lk + 0][lrow] = av.x;
        As[lk + 1][lrow] = av.y;
        As[lk + 2][lrow] = av.z;
        As[lk + 3][lrow] = av.w;

        float4 bv = *(const float4*)&W[(k0 + brow) * DF + colOff + bcol];
        *(float4*)&Bs[brow][bcol] = bv;
        __syncthreads();

        #pragma unroll
        for (int kk = 0; kk < 16; kk++) {
            float4 a = *(const float4*)&As[kk][ty * 4];
            float4 b = *(const float4*)&Bs[kk][tx * 4];
            acc[0][0] += a.x * b.x; acc[0][1] += a.x * b.y; acc[0][2] += a.x * b.z; acc[0][3] += a.x * b.w;
            acc[1][0] += a.y * b.x; acc[1][1] += a.y * b.y; acc[1][2] += a.y * b.z; acc[1][3] += a.y * b.w;
            acc[2][0] += a.z * b.x; acc[2][1] += a.z * b.y; acc[2][2] += a.z * b.z; acc[2][3] += a.z * b.w;
            acc[3][0] += a.w * b.x; acc[3][1] += a.w * b.y; acc[3][2] += a.w * b.z; acc[3][3] += a.w * b.w;
        }
        __syncthreads();
    }

    int c = colOff + tx * 4;
    #pragma unroll
    for (int i = 0; i < 4; i++) {
        int r = rowBase + ty * 4 + i;
        if (r < N) {
            float4 o = make_float4(acc[i][0], acc[i][1], acc[i][2], acc[i][3]);
            if (by >= 2) {
                o.x += bias[c];     o.y += bias[c + 1];
                o.z += bias[c + 2]; o.w += bias[c + 3];
            }
            *(float4*)&Out[r * DF + c] = o;
        }
    }
}

// ---------------- per-node attention dots -------------------------
// one warp per node; lane t: head = t>>3, 4 channels at (t&7)*4.
__global__ void dot_kernel(const float* __restrict__ a_src,
                           const float* __restrict__ a_dst,
                           int N)
{
    int warpId = (blockIdx.x * blockDim.x + threadIdx.x) >> 5;
    int lane = threadIdx.x & 31;
    if (warpId >= N) return;

    float4 hv = *(const float4*)&g_h[warpId * DF + lane * 4];
    float4 as = ((const float4*)a_src)[lane];
    float4 ad = ((const float4*)a_dst)[lane];

    float ps = hv.x * as.x + hv.y * as.y + hv.z * as.z + hv.w * as.w;
    float pd = hv.x * ad.x + hv.y * ad.y + hv.z * ad.z + hv.w * ad.w;

    ps += __shfl_xor_sync(0xffffffffu, ps, 1);
    ps += __shfl_xor_sync(0xffffffffu, ps, 2);
    ps += __shfl_xor_sync(0xffffffffu, ps, 4);
    pd += __shfl_xor_sync(0xffffffffu, pd, 1);
    pd += __shfl_xor_sync(0xffffffffu, pd, 2);
    pd += __shfl_xor_sync(0xffffffffu, pd, 4);

    if ((lane & 7) == 0) {
        int head = lane >> 3;
        g_ds[warpId * HEADS + head] = ps;
        g_dd[warpId * HEADS + head] = pd;
    }
}

// ---------------- edge pass ---------------------------------------
// one warp per edge. Unnormalized: acc[dst] += e * h[src]; den[dst] += e.
// (softmax is shift-invariant -> no segment-max pass needed)
__global__ void edge_kernel(const int* __restrict__ src,
                            const int* __restrict__ dst,
                            int E)
{
    int warpId = (blockIdx.x * blockDim.x + threadIdx.x) >> 5;
    int lane = threadIdx.x & 31;
    if (warpId >= E) return;

    int s = src[warpId];
    int d = dst[warpId];
    int head = lane >> 3;

    float z = g_ds[s * HEADS + head] + g_dd[d * HEADS + head];
    z = (z >= 0.f) ? z : NEG_SLOPE * z;
    float w = expf(z);

    if ((lane & 7) == 0)
        atomicAdd(&g_den[d * HEADS + head], w);

    float4 v = *(const float4*)&g_h[s * DF + lane * 4];
    float a0 = w * v.x, a1 = w * v.y, a2 = w * v.z, a3 = w * v.w;
    float* p = &g_acc[d * DF + lane * 4];
    asm volatile("red.global.add.v4.f32 [%0], {%1, %2, %3, %4};"
                 :: "l"(p), "f"(a0), "f"(a1), "f"(a2), "f"(a3) : "memory");
}

// ---------------- finalize ----------------------------------------
// d_out (already holds x@W_lin + bias) += acc / denom  (0 if node has no in-edges)
__global__ void final_kernel(float* __restrict__ out, int N)
{
    int idx = blockIdx.x * blockDim.x + threadIdx.x;   // float4 index over N*32
    if (idx >= N * 32) return;
    int n = idx >> 5;
    int head = (idx >> 3) & 3;
    float den = g_den[n * HEADS + head];
    float inv = (den > 0.f) ? (1.0f / den) : 0.f;
    float4 a = ((const float4*)g_acc)[idx];
    float4 o = ((float4*)out)[idx];
    o.x += a.x * inv;
    o.y += a.y * inv;
    o.z += a.z * inv;
    o.w += a.w * inv;
    ((float4*)out)[idx] = o;
}

// ------------------------------------------------------------------
extern "C" void kernel_launch(void* const* d_in, const int* in_sizes, int n_in,
                              void* d_out, int out_size)
{
    const float* x       = (const float*)d_in[0];
    const float* W_embed = (const float*)d_in[1];
    const float* a_src   = (const float*)d_in[2];
    const float* a_dst   = (const float*)d_in[3];
    const float* W_lin   = (const float*)d_in[4];
    const float* bias    = (const float*)d_in[5];
    const int*   src     = (const int*)d_in[6];
    const int*   dst     = (const int*)d_in[7];
    float* out = (float*)d_out;

    int N = in_sizes[0] / DF;
    int E = in_sizes[6];

    // 1. zero accumulators (N*32 float4 for acc + N float4 for denom)
    int z4 = N * 33;
    zero_kernel<<<(z4 + 255) / 256, 256>>>(N);

    // 2. fused dual GEMM: h -> g_h, lin+bias -> d_out
    dim3 ggrid((N + 63) / 64, 4);
    gemm_kernel<<<ggrid, 256>>>(x, W_embed, W_lin, bias, out, N);

    // 3. attention dots (one warp per node)
    dot_kernel<<<(N + 7) / 8, 256>>>(a_src, a_dst, N);

    // 4. edge pass (one warp per edge)
    edge_kernel<<<(E + 7) / 8, 256>>>(src, dst, E);

    // 5. finalize
    final_kernel<<<(N * 32 + 255) / 256, 256>>>(out, N);
}